// round 1
// baseline (speedup 1.0000x reference)
#include <cuda_runtime.h>
#include <cstdint>

#define T_STEPS  64
#define N_ROWS   2048
#define DR2      512
#define KDIM     1024
#define M_TILE   16
#define KC       32
#define NTHREADS 256
#define XPITCH   516          // DR2 + 4 pad: de-aliases 512-stride banks
#define NCHUNKS  (KDIM / KC)  // 32

#define DECAY_F 0.6065306597126334f

__device__ __forceinline__ unsigned smem_u32(const void* p) {
    return (unsigned)__cvta_generic_to_shared(p);
}

__global__ void __launch_bounds__(NTHREADS, 1)
evo_kernel(const float* __restrict__ g_static,  // [T, N, DR2]
           const float* __restrict__ g_thr,     // [T, N, 1]
           const float* __restrict__ g_h0,      // [N, DR2]
           const float* __restrict__ g_w1,      // [KDIM, DR2]
           float* __restrict__ g_out)
{
    extern __shared__ float smem[];
    float* h_sh   = smem;                       // M_TILE * XPITCH
    float* s_sh   = h_sh + M_TILE * XPITCH;     // M_TILE * XPITCH
    float* w_sh   = s_sh + M_TILE * XPITCH;     // 2 * KC * DR2 (double buffer)
    float* thr_sh = w_sh + 2 * KC * DR2;        // M_TILE

    float* out_dyn  = g_out;                                     // [T,N,DR2]
    float* out_fin  = g_out + (size_t)T_STEPS * N_ROWS * DR2;    // [N,DR2]
    float* out_diff = out_fin + (size_t)N_ROWS * DR2;            // [T-1,N,DR2]

    const int tid = threadIdx.x;
    const int n0  = blockIdx.x * M_TILE;
    const int mt  = tid & 3;       // 4 row-groups (broadcast-friendly within warp)
    const int jt  = tid >> 2;      // 64 column-threads

    // ---- init: h0 -> h_sh, and dynamic[0] = h0 (faithful to reference) ----
    {
        const float4* src  = (const float4*)(g_h0 + (size_t)n0 * DR2);
        float4* dyn0       = (float4*)(out_dyn + (size_t)n0 * DR2);
        for (int i = tid; i < M_TILE * DR2 / 4; i += NTHREADS) {
            float4 v = src[i];
            int m = i >> 7;                       // 128 float4 per row
            ((float4*)(h_sh + m * XPITCH))[i & 127] = v;
            dyn0[i] = v;
        }
    }
    __syncthreads();

    unsigned long long acc[4][4];   // 4 m x 4 float2-pairs (j = jt*2 + 128*jj)

    for (int t = 0; t < T_STEPS; ++t) {
        // ---- load static tile + thresholds for this step ----
        {
            const float4* src = (const float4*)(g_static + ((size_t)t * N_ROWS + n0) * DR2);
            for (int i = tid; i < M_TILE * DR2 / 4; i += NTHREADS) {
                int m = i >> 7;
                ((float4*)(s_sh + m * XPITCH))[i & 127] = src[i];
            }
            if (tid < M_TILE)
                thr_sh[tid] = g_thr[(size_t)t * N_ROWS + n0 + tid];
        }

        #pragma unroll
        for (int a = 0; a < 4; ++a)
            #pragma unroll
            for (int b = 0; b < 4; ++b) acc[a][b] = 0ull;

        // ---- prologue: async-copy w1 chunk 0 into buffer 0 ----
        {
            unsigned dst = smem_u32(w_sh) + tid * 16;
            const char* src = (const char*)g_w1 + tid * 16;
            #pragma unroll
            for (int r = 0; r < (KC * DR2 / 4) / NTHREADS; ++r)
                asm volatile("cp.async.cg.shared.global [%0], [%1], 16;"
                             :: "r"(dst + r * NTHREADS * 16),
                                "l"(src + (size_t)r * NTHREADS * 16));
            asm volatile("cp.async.commit_group;");
        }

        const float* xbase_h = h_sh + mt * 4 * XPITCH;
        const float* xbase_s = s_sh + mt * 4 * XPITCH;

        for (int c = 0; c < NCHUNKS; ++c) {
            // prefetch chunk c+1 into the other buffer, then wait for chunk c
            if (c + 1 < NCHUNKS) {
                float* wb_next = w_sh + ((c + 1) & 1) * (KC * DR2);
                unsigned dst = smem_u32(wb_next) + tid * 16;
                const char* src = (const char*)(g_w1 + (size_t)(c + 1) * KC * DR2) + tid * 16;
                #pragma unroll
                for (int r = 0; r < (KC * DR2 / 4) / NTHREADS; ++r)
                    asm volatile("cp.async.cg.shared.global [%0], [%1], 16;"
                                 :: "r"(dst + r * NTHREADS * 16),
                                    "l"(src + (size_t)r * NTHREADS * 16));
                asm volatile("cp.async.commit_group;");
                asm volatile("cp.async.wait_group 1;" ::: "memory");
            } else {
                asm volatile("cp.async.wait_group 0;" ::: "memory");
            }
            __syncthreads();

            const float* wb = w_sh + (c & 1) * (KC * DR2);
            const float* xb = (c < NCHUNKS / 2) ? (xbase_h + c * KC)
                                                : (xbase_s + (c - NCHUNKS / 2) * KC);

            #pragma unroll 8
            for (int kk = 0; kk < KC; ++kk) {
                unsigned long long xv[4];
                #pragma unroll
                for (int mi = 0; mi < 4; ++mi) {
                    unsigned xb32 = __float_as_uint(xb[mi * XPITCH + kk]);
                    asm("mov.b64 %0, {%1, %1};" : "=l"(xv[mi]) : "r"(xb32));
                }
                const unsigned long long* wrow =
                    (const unsigned long long*)(wb + (size_t)kk * DR2);
                unsigned long long wv[4];
                #pragma unroll
                for (int jj = 0; jj < 4; ++jj) wv[jj] = wrow[jt + 64 * jj];
                #pragma unroll
                for (int mi = 0; mi < 4; ++mi)
                    #pragma unroll
                    for (int jj = 0; jj < 4; ++jj)
                        asm("fma.rn.f32x2 %0, %1, %2, %0;"
                            : "+l"(acc[mi][jj]) : "l"(xv[mi]), "l"(wv[jj]));
            }
            __syncthreads();   // all FMAs on this buffer done before it is refilled
        }

        // ---- epilogue: gate, update h, write dynamic/diff/final ----
        {
            float* dynp  = out_dyn  + (size_t)t * N_ROWS * DR2;
            float* diffp = out_diff + (size_t)(t - 1) * N_ROWS * DR2;
            #pragma unroll
            for (int mi = 0; mi < 4; ++mi) {
                int m = mt * 4 + mi;
                float th = thr_sh[m];
                float om = 1.0f - th;
                size_t rowoff = (size_t)(n0 + m) * DR2;
                float* hrow = h_sh + m * XPITCH;
                #pragma unroll
                for (int jj = 0; jj < 4; ++jj) {
                    int j = jt * 2 + 128 * jj;
                    float2 hold = *(float2*)(hrow + j);
                    unsigned lo32, hi32;
                    asm("mov.b64 {%0, %1}, %2;" : "=r"(lo32), "=r"(hi32) : "l"(acc[mi][jj]));
                    float mlo = __uint_as_float(lo32);
                    float mhi = __uint_as_float(hi32);
                    float nlo = DECAY_F / (1.0f + __expf(-(mlo * th + hold.x * om)));
                    float nhi = DECAY_F / (1.0f + __expf(-(mhi * th + hold.y * om)));
                    *(float2*)(hrow + j) = make_float2(nlo, nhi);
                    if (t > 0) {
                        *(float2*)(dynp  + rowoff + j) = make_float2(nlo, nhi);
                        *(float2*)(diffp + rowoff + j) = make_float2(nlo - hold.x, nhi - hold.y);
                    }
                    if (t == T_STEPS - 1)
                        *(float2*)(out_fin + rowoff + j) = make_float2(nlo, nhi);
                }
            }
        }
        __syncthreads();   // protect s_sh/thr_sh/h_sh before next step reuses them
    }
}

extern "C" void kernel_launch(void* const* d_in, const int* in_sizes, int n_in,
                              void* d_out, int out_size)
{
    (void)in_sizes; (void)n_in; (void)out_size;
    const float* g_static = (const float*)d_in[0];
    const float* g_thr    = (const float*)d_in[1];
    const float* g_h0     = (const float*)d_in[2];
    const float* g_w1     = (const float*)d_in[3];
    float* out = (float*)d_out;

    size_t smem = (size_t)(2 * M_TILE * XPITCH + 2 * KC * DR2 + M_TILE) * sizeof(float);
    cudaFuncSetAttribute(evo_kernel, cudaFuncAttributeMaxDynamicSharedMemorySize, (int)smem);
    evo_kernel<<<N_ROWS / M_TILE, NTHREADS, smem>>>(g_static, g_thr, g_h0, g_w1, out);
}

// round 4
// speedup vs baseline: 1.9491x; 1.9491x over previous
#include <cuda_runtime.h>
#include <cstdint>

#define T_STEPS  64
#define N_ROWS   2048
#define DR2      512
#define KHALF    512            // K per pass (h-half / static-half)
#define M_TILE   16
#define KC       32
#define NTHREADS 256
#define XPITCH   516            // DR2 + 4 pad
#define NCHUNKS2 (KHALF / KC)   // 16

#define DECAY_F 0.6065306597126334f

// ---------------- pass 1: G = static @ w1[512:1024]  (plain GEMM) ----------------
#define BM 128
#define BN 128
#define BK 16

__device__ __forceinline__ unsigned smem_u32(const void* p) {
    return (unsigned)__cvta_generic_to_shared(p);
}
__device__ __forceinline__ unsigned long long dup2(float x) {
    unsigned long long r; asm("mov.b64 %0, {%1, %1};" : "=l"(r) : "f"(x)); return r;
}
__device__ __forceinline__ unsigned long long pack2(float x, float y) {
    unsigned long long r; asm("mov.b64 %0, {%1, %2};" : "=l"(r) : "f"(x), "f"(y)); return r;
}

__global__ void __launch_bounds__(256, 2)
gemm_static_kernel(const float* __restrict__ A,   // [131072, 512] = static flattened
                   const float* __restrict__ W,   // w1 + 512*512 (bottom half)
                   float* __restrict__ C)         // out_dyn region [131072, 512]
{
    __shared__ float As[2][BM * BK];   // [m][k], pitch 16
    __shared__ float Bs[2][BK * BN];   // [k][n], pitch 128

    const int tid = threadIdx.x;
    const int tx = tid & 15;           // 16 col-threads * 8 cols
    const int ty = tid >> 4;           // 16 row-threads * 8 rows
    const long m0 = (long)blockIdx.x * BM;
    const int  n0 = blockIdx.y * BN;

    auto load_chunk = [&](int buf, int k0) {
        // A tile: 512 float4, 2 per thread. row = idx>>2, kq = idx&3
        #pragma unroll
        for (int r = 0; r < 2; ++r) {
            int idx = tid + r * 256;
            int row = idx >> 2, kq = idx & 3;
            unsigned dst = smem_u32(&As[buf][row * BK + kq * 4]);
            const char* src = (const char*)(A + (m0 + row) * DR2 + k0 + kq * 4);
            asm volatile("cp.async.cg.shared.global [%0], [%1], 16;" :: "r"(dst), "l"(src));
        }
        // B tile: 512 float4. k = idx>>5, nq = idx&31
        #pragma unroll
        for (int r = 0; r < 2; ++r) {
            int idx = tid + r * 256;
            int k = idx >> 5, nq = idx & 31;
            unsigned dst = smem_u32(&Bs[buf][k * BN + nq * 4]);
            const char* src = (const char*)(W + (size_t)(k0 + k) * DR2 + n0 + nq * 4);
            asm volatile("cp.async.cg.shared.global [%0], [%1], 16;" :: "r"(dst), "l"(src));
        }
        asm volatile("cp.async.commit_group;");
    };

    unsigned long long acc[8][4];
    #pragma unroll
    for (int i = 0; i < 8; ++i)
        #pragma unroll
        for (int j = 0; j < 4; ++j) acc[i][j] = 0ull;

    load_chunk(0, 0);

    const int nchunks = KHALF / BK;    // 32
    for (int c = 0; c < nchunks; ++c) {
        if (c + 1 < nchunks) {
            load_chunk((c + 1) & 1, (c + 1) * BK);
            asm volatile("cp.async.wait_group 1;" ::: "memory");
        } else {
            asm volatile("cp.async.wait_group 0;" ::: "memory");
        }
        __syncthreads();

        const float* as = As[c & 1];
        const float* bs = Bs[c & 1];

        #pragma unroll
        for (int k = 0; k < BK; ++k) {
            const float* brow = bs + k * BN + tx * 8;
            float4 b0 = *(const float4*)(brow);
            float4 b1 = *(const float4*)(brow + 4);
            unsigned long long bv[4] = { pack2(b0.x, b0.y), pack2(b0.z, b0.w),
                                         pack2(b1.x, b1.y), pack2(b1.z, b1.w) };
            #pragma unroll
            for (int i = 0; i < 8; ++i) {
                unsigned long long av = dup2(as[(ty * 8 + i) * BK + k]);
                #pragma unroll
                for (int j = 0; j < 4; ++j)
                    asm("fma.rn.f32x2 %0, %1, %2, %0;"
                        : "+l"(acc[i][j]) : "l"(av), "l"(bv[j]));
            }
        }
        __syncthreads();
    }

    #pragma unroll
    for (int i = 0; i < 8; ++i) {
        float o[8];
        #pragma unroll
        for (int j = 0; j < 4; ++j) {
            unsigned lo, hi;
            asm("mov.b64 {%0, %1}, %2;" : "=r"(lo), "=r"(hi) : "l"(acc[i][j]));
            o[2 * j]     = __uint_as_float(lo);
            o[2 * j + 1] = __uint_as_float(hi);
        }
        float* crow = C + (m0 + ty * 8 + i) * DR2 + n0 + tx * 8;
        *(float4*)(crow)     = make_float4(o[0], o[1], o[2], o[3]);
        *(float4*)(crow + 4) = make_float4(o[4], o[5], o[6], o[7]);
    }
}

// ---------------- pass 2: serial recurrence, K = 512 (h half), acc init from G ----------------

__global__ void __launch_bounds__(NTHREADS, 1)
evo_kernel(const float* __restrict__ g_thr,     // [T, N, 1]
           const float* __restrict__ g_h0,      // [N, DR2]
           const float* __restrict__ g_w1,      // [KDIM, DR2] (top 512 rows used)
           float* __restrict__ g_out)
{
    extern __shared__ float smem[];
    float* h_sh   = smem;                       // M_TILE * XPITCH
    float* w_sh   = h_sh + M_TILE * XPITCH;     // 2 * KC * DR2 (double buffer)
    float* thr_sh = w_sh + 2 * KC * DR2;        // M_TILE

    float* out_dyn  = g_out;                                     // [T,N,DR2] (holds G, overwritten)
    float* out_fin  = g_out + (size_t)T_STEPS * N_ROWS * DR2;
    float* out_diff = out_fin + (size_t)N_ROWS * DR2;

    const int tid = threadIdx.x;
    const int n0  = blockIdx.x * M_TILE;
    const int mt  = tid & 3;
    const int jt  = tid >> 2;

    // init h_sh from h0
    {
        const float4* src = (const float4*)(g_h0 + (size_t)n0 * DR2);
        for (int i = tid; i < M_TILE * DR2 / 4; i += NTHREADS) {
            int m = i >> 7;
            ((float4*)(h_sh + m * XPITCH))[i & 127] = src[i];
        }
    }
    __syncthreads();

    unsigned long long acc[4][4];

    for (int t = 0; t < T_STEPS; ++t) {
        if (tid < M_TILE)
            thr_sh[tid] = g_thr[(size_t)t * N_ROWS + n0 + tid];

        // prologue: async-copy w chunk 0
        {
            unsigned dst = smem_u32(w_sh) + tid * 16;
            const char* src = (const char*)g_w1 + tid * 16;
            #pragma unroll
            for (int r = 0; r < (KC * DR2 / 4) / NTHREADS; ++r)
                asm volatile("cp.async.cg.shared.global [%0], [%1], 16;"
                             :: "r"(dst + r * NTHREADS * 16),
                                "l"(src + (size_t)r * NTHREADS * 16));
            asm volatile("cp.async.commit_group;");
        }

        // init acc from G (precomputed static half, staged in out_dyn[t])
        {
            const float* gsrc = out_dyn + (size_t)t * N_ROWS * DR2;
            #pragma unroll
            for (int mi = 0; mi < 4; ++mi) {
                size_t rowoff = (size_t)(n0 + mt * 4 + mi) * DR2;
                #pragma unroll
                for (int jj = 0; jj < 4; ++jj) {
                    int j = jt * 2 + 128 * jj;
                    acc[mi][jj] = *(const unsigned long long*)(gsrc + rowoff + j);
                }
            }
        }

        const float* xbase_h = h_sh + mt * 4 * XPITCH;

        for (int c = 0; c < NCHUNKS2; ++c) {
            if (c + 1 < NCHUNKS2) {
                float* wb_next = w_sh + ((c + 1) & 1) * (KC * DR2);
                unsigned dst = smem_u32(wb_next) + tid * 16;
                const char* src = (const char*)(g_w1 + (size_t)(c + 1) * KC * DR2) + tid * 16;
                #pragma unroll
                for (int r = 0; r < (KC * DR2 / 4) / NTHREADS; ++r)
                    asm volatile("cp.async.cg.shared.global [%0], [%1], 16;"
                                 :: "r"(dst + r * NTHREADS * 16),
                                    "l"(src + (size_t)r * NTHREADS * 16));
                asm volatile("cp.async.commit_group;");
                asm volatile("cp.async.wait_group 1;" ::: "memory");
            } else {
                asm volatile("cp.async.wait_group 0;" ::: "memory");
            }
            __syncthreads();

            const float* wb = w_sh + (c & 1) * (KC * DR2);
            const float* xb = xbase_h + c * KC;

            #pragma unroll 8
            for (int kk = 0; kk < KC; ++kk) {
                unsigned long long xv[4];
                #pragma unroll
                for (int mi = 0; mi < 4; ++mi)
                    xv[mi] = dup2(xb[mi * XPITCH + kk]);
                const unsigned long long* wrow =
                    (const unsigned long long*)(wb + (size_t)kk * DR2);
                unsigned long long wv[4];
                #pragma unroll
                for (int jj = 0; jj < 4; ++jj) wv[jj] = wrow[jt + 64 * jj];
                #pragma unroll
                for (int mi = 0; mi < 4; ++mi)
                    #pragma unroll
                    for (int jj = 0; jj < 4; ++jj)
                        asm("fma.rn.f32x2 %0, %1, %2, %0;"
                            : "+l"(acc[mi][jj]) : "l"(xv[mi]), "l"(wv[jj]));
            }
            __syncthreads();
        }

        // epilogue: gate, update h, write outputs
        {
            float* dynp  = out_dyn  + (size_t)t * N_ROWS * DR2;
            float* diffp = out_diff + (size_t)(t - 1) * N_ROWS * DR2;
            #pragma unroll
            for (int mi = 0; mi < 4; ++mi) {
                int m = mt * 4 + mi;
                float th = thr_sh[m];
                float om = 1.0f - th;
                size_t rowoff = (size_t)(n0 + m) * DR2;
                float* hrow = h_sh + m * XPITCH;
                #pragma unroll
                for (int jj = 0; jj < 4; ++jj) {
                    int j = jt * 2 + 128 * jj;
                    float2 hold = *(float2*)(hrow + j);
                    unsigned lo32, hi32;
                    asm("mov.b64 {%0, %1}, %2;" : "=r"(lo32), "=r"(hi32) : "l"(acc[mi][jj]));
                    float mlo = __uint_as_float(lo32);
                    float mhi = __uint_as_float(hi32);
                    float nlo = DECAY_F / (1.0f + __expf(-(mlo * th + hold.x * om)));
                    float nhi = DECAY_F / (1.0f + __expf(-(mhi * th + hold.y * om)));
                    *(float2*)(hrow + j) = make_float2(nlo, nhi);
                    if (t > 0) {
                        *(float2*)(dynp  + rowoff + j) = make_float2(nlo, nhi);
                        *(float2*)(diffp + rowoff + j) = make_float2(nlo - hold.x, nhi - hold.y);
                    } else {
                        // dynamic[0] = h0 (faithful to reference); G[0] already consumed
                        *(float2*)(dynp + rowoff + j) = hold;
                    }
                    if (t == T_STEPS - 1)
                        *(float2*)(out_fin + rowoff + j) = make_float2(nlo, nhi);
                }
            }
        }
        __syncthreads();
    }
}

extern "C" void kernel_launch(void* const* d_in, const int* in_sizes, int n_in,
                              void* d_out, int out_size)
{
    (void)in_sizes; (void)n_in; (void)out_size;
    const float* g_static = (const float*)d_in[0];
    const float* g_thr    = (const float*)d_in[1];
    const float* g_h0     = (const float*)d_in[2];
    const float* g_w1     = (const float*)d_in[3];
    float* out = (float*)d_out;

    // pass 1: G = static @ w1_bottom -> staged in the dynamic-output region
    dim3 grid1(T_STEPS * N_ROWS / BM, DR2 / BN);
    gemm_static_kernel<<<grid1, 256>>>(g_static, g_w1 + (size_t)KHALF * DR2, out);

    // pass 2: serial recurrence over the h half
    size_t smem = (size_t)(M_TILE * XPITCH + 2 * KC * DR2 + M_TILE) * sizeof(float);
    cudaFuncSetAttribute(evo_kernel, cudaFuncAttributeMaxDynamicSharedMemorySize, (int)smem);
    evo_kernel<<<N_ROWS / M_TILE, NTHREADS, smem>>>(g_thr, g_h0, g_w1, out);
}